// round 5
// baseline (speedup 1.0000x reference)
#include <cuda_runtime.h>
#include <math.h>

// ---------------------------------------------------------------------------
// ANI ensemble MLP energy on GB300 (fp32 SIMT, cp.async pipelined across
// chunks, layers AND ensembles; 2-launch cycle: k_bin -> k_compute).
// The last k_compute block writes the scalar output and resets the device
// globals for the next call (statics are zero-initialized for call #1).
// Output = sum_a mean_e net_{species[a]}^{(e)}(aev[a]).
// ---------------------------------------------------------------------------

#define NMAX 100000
constexpr int S_ = 4;
constexpr int E_ = 8;
constexpr int D0 = 384, D1 = 160, D2 = 128, D3 = 96;
constexpr int TM = 64;        // atoms per block
constexpr int PAD = 68;       // smem activation row stride (floats)
constexpr int KC = 32;        // K-chunk for weight staging
constexpr int NT = 512;       // 16 warps: warp = output group, lane = 2 atoms

__device__ int    g_cnt[S_];      // zero-initialized
__device__ int    g_idx[S_ * NMAX];
__device__ double g_sum;          // zero-initialized
__device__ int    g_done;         // zero-initialized

__global__ void k_bin(const int* __restrict__ species, int n) {
    int i = blockIdx.x * blockDim.x + threadIdx.x;
    int lane = threadIdx.x & 31;
    unsigned active = __ballot_sync(0xffffffffu, i < n);
    if (i < n) {
        int s = species[i] & (S_ - 1);
        unsigned peers = __match_any_sync(active, s);
        int leader = __ffs(peers) - 1;
        int rank = __popc(peers & ((1u << lane) - 1));
        int base = 0;
        if (lane == leader) base = atomicAdd(&g_cnt[s], __popc(peers));
        base = __shfl_sync(peers, base, leader);
        g_idx[s * NMAX + base + rank] = i;
    }
}

__device__ __forceinline__ float celu_f(float x) {
    // jax.nn.celu(x, 0.1) = x>0 ? x : 0.1*expm1(x/0.1)
    return x > 0.0f ? x : 0.1f * expm1f(x * 10.0f);
}

__device__ __forceinline__ void cp16(float* smem_dst, const float4* gsrc) {
    unsigned a = (unsigned)__cvta_generic_to_shared(smem_dst);
    asm volatile("cp.async.cg.shared.global [%0], [%1], 16;\n" :: "r"(a), "l"(gsrc));
}
__device__ __forceinline__ void cp_commit() {
    asm volatile("cp.async.commit_group;\n");
}
__device__ __forceinline__ void cp_wait1() {
    asm volatile("cp.async.wait_group 1;\n");
}

// One dense layer: sOut[n][atom] = celu(sIn[k][atom] @ gW[K][N] + sB[n]).
// Activations transposed [feature][atom], stride PAD.
// warp wid (0..15) owns outputs TN*wid..TN*wid+TN-1; lane owns atoms 2l,2l+1.
// PIPELINE INVARIANT at entry: this layer's chunk 0 is in bufs[p] with its
// cp.async group still outstanding (exactly 1 group in flight). At exit the
// same holds for nextW's chunk 0 (nextNV4 float4s).
template<int K, int N, int TN>
__device__ __forceinline__ void gemm_layer(
    const float* __restrict__ sIn, const float* __restrict__ gW,
    const float* __restrict__ sB, float* __restrict__ sOut,
    float* __restrict__ sW0, float* __restrict__ sW1, int& p,
    const float4* __restrict__ nextW, int nextNV4,
    int tid, int lane, int wid) {

    static_assert((TN & 1) == 0, "TN even for float2 weight loads");
    constexpr int C   = K / KC;       // chunks
    constexpr int NV4 = KC * N / 4;   // float4 per chunk

    float acc[2][TN];
#pragma unroll
    for (int i = 0; i < 2; i++)
#pragma unroll
        for (int j = 0; j < TN; j++) acc[i][j] = 0.0f;

    const float4* gW4 = reinterpret_cast<const float4*>(gW);
    float* bufs[2] = { sW0, sW1 };

    for (int c = 0; c < C; c++) {
        // prefetch chunk c+1 (or next layer's chunk 0) into the ping buffer
        const float4* src; int sn;
        if (c + 1 < C) { src = gW4 + (size_t)(c + 1) * NV4; sn = NV4; }
        else           { src = nextW;                        sn = nextNV4; }
        float* dst = bufs[p ^ 1];
        for (int l = tid; l < sn; l += NT) cp16(dst + 4 * l, src + l);
        cp_commit();
        cp_wait1();            // oldest group (chunk c) now resident
        __syncthreads();

        const float* sW = bufs[p];
        const float* inBase = sIn + c * KC * PAD + 2 * lane;
#pragma unroll 4
        for (int kk = 0; kk < KC; kk++) {
            float2 av = *reinterpret_cast<const float2*>(inBase + kk * PAD);
            const float2* wr = reinterpret_cast<const float2*>(sW + kk * N + TN * wid);
            float2 bv[TN / 2];
#pragma unroll
            for (int j = 0; j < TN / 2; j++) bv[j] = wr[j];
#pragma unroll
            for (int j = 0; j < TN / 2; j++) {
                acc[0][2 * j]     += av.x * bv[j].x;
                acc[1][2 * j]     += av.y * bv[j].x;
                acc[0][2 * j + 1] += av.x * bv[j].y;
                acc[1][2 * j + 1] += av.y * bv[j].y;
            }
        }
        __syncthreads();
        p ^= 1;
    }

    // epilogue: bias + CELU, write transposed (2 atoms -> STS.64)
#pragma unroll
    for (int j = 0; j < TN; j++) {
        float bb = sB[TN * wid + j];
        float2 o;
        o.x = celu_f(acc[0][j] + bb);
        o.y = celu_f(acc[1][j] + bb);
        *reinterpret_cast<float2*>(sOut + (TN * wid + j) * PAD + 2 * lane) = o;
    }
    __syncthreads();
}

__global__ void __launch_bounds__(NT, 1)
k_compute(const float* __restrict__ aev,
          const float* __restrict__ W1, const float* __restrict__ B1,
          const float* __restrict__ W2, const float* __restrict__ B2,
          const float* __restrict__ W3, const float* __restrict__ B3,
          const float* __restrict__ W4, const float* __restrict__ B4,
          float* __restrict__ out) {
    extern __shared__ float sm[];
    float* sA     = sm;                   // D0*PAD (AEV, persists all ensembles)
    float* sHa    = sA  + D0 * PAD;       // D1*PAD (H1, later H3)
    float* sHb    = sHa + D1 * PAD;       // D2*PAD (H2)
    float* sW0    = sHb + D2 * PAD;       // KC*D1
    float* sW1    = sW0 + KC * D1;        // KC*D1
    float* sBias  = sW1 + KC * D1;        // D1+D2+D3 floats
    float* sW4b   = sBias + (D1 + D2 + D3);
    float* sAtomE = sW4b + D3;
    int*   sIdx   = reinterpret_cast<int*>(sAtomE + TM);

    const int s    = blockIdx.y;
    const int tid  = threadIdx.x;
    const int lane = tid & 31;
    const int wid  = tid >> 5;
    const int cnt  = g_cnt[s];
    const int base = blockIdx.x * TM;

    constexpr int NV4_1 = KC * D1 / 4;  // 1280
    constexpr int NV4_2 = KC * D2 / 4;  // 1024
    constexpr int NV4_3 = KC * D3 / 4;  //  768

    if (base < cnt) {
        const int nvalid = min(TM, cnt - base);

        if (tid < TM) {
            int j = min(tid, nvalid - 1);   // padding atoms duplicate a valid one
            sIdx[tid]   = g_idx[s * NMAX + base + j];
            sAtomE[tid] = 0.0f;
        }
        __syncthreads();

        // kick off the weight pipeline: W1(e=0) chunk 0 into sW0
        {
            const float4* w1_0 = reinterpret_cast<const float4*>(W1 + (long)s * E_ * D0 * D1);
            for (int l = tid; l < NV4_1; l += NT) cp16(sW0 + 4 * l, w1_0 + l);
            cp_commit();
        }

        // Gather AEV tile, store transposed [k][atom] (overlaps with prefetch)
        constexpr int KV = D0 / 4;
        const float4* aev4 = reinterpret_cast<const float4*>(aev);
        for (int l = tid; l < TM * KV; l += NT) {
            int a = l / KV, kq = l % KV;
            float4 v = aev4[(long)sIdx[a] * KV + kq];
            int kb = 4 * kq;
            sA[(kb + 0) * PAD + a] = v.x;
            sA[(kb + 1) * PAD + a] = v.y;
            sA[(kb + 2) * PAD + a] = v.z;
            sA[(kb + 3) * PAD + a] = v.w;
        }
        __syncthreads();

        int p = 0;
        for (int e = 0; e < E_; e++) {
            const int se = s * E_ + e;
            const int seN = s * E_ + ((e + 1) & (E_ - 1));  // next ensemble (wraps)

            // stage biases + final-layer weights (overlaps in-flight prefetch)
            if (tid < D1)                sBias[tid] = B1[se * D1 + tid];
            else if (tid < D1 + D2)      sBias[tid] = B2[se * D2 + tid - D1];
            else if (tid < D1 + D2 + D3) sBias[tid] = B3[se * D3 + tid - D1 - D2];
            if (tid >= NT - D3) sW4b[tid - (NT - D3)] = W4[se * D3 + tid - (NT - D3)];
            __syncthreads();

            gemm_layer<D0, D1, 10>(sA,  W1 + (long)se * D0 * D1, sBias,           sHa,
                                   sW0, sW1, p,
                                   reinterpret_cast<const float4*>(W2 + (long)se * D1 * D2), NV4_2,
                                   tid, lane, wid);
            gemm_layer<D1, D2,  8>(sHa, W2 + (long)se * D1 * D2, sBias + D1,      sHb,
                                   sW0, sW1, p,
                                   reinterpret_cast<const float4*>(W3 + (long)se * D2 * D3), NV4_3,
                                   tid, lane, wid);
            gemm_layer<D2, D3,  6>(sHb, W3 + (long)se * D2 * D3, sBias + D1 + D2, sHa,
                                   sW0, sW1, p,
                                   reinterpret_cast<const float4*>(W1 + (long)seN * D0 * D1), NV4_1,
                                   tid, lane, wid);

            // final layer: per-atom dot(h3, w4) + b4; 8 threads per atom
            const float gb4 = B4[se];
            int atom = tid >> 3, q = tid & 7;
            float v = 0.0f;
#pragma unroll
            for (int m = 0; m < 12; m++) {
                int k = q * 12 + m;
                v += sHa[k * PAD + atom] * sW4b[k];
            }
            v += __shfl_xor_sync(0xffffffffu, v, 1);
            v += __shfl_xor_sync(0xffffffffu, v, 2);
            v += __shfl_xor_sync(0xffffffffu, v, 4);
            if (q == 0) sAtomE[atom] += v + gb4;
            __syncthreads();
        }

        // block reduction over valid atoms; mean over E via *0.125
        if (tid < 32) {
            float v = 0.0f;
            if (tid < nvalid)      v += sAtomE[tid];
            if (tid + 32 < nvalid) v += sAtomE[tid + 32];
#pragma unroll
            for (int off = 16; off > 0; off >>= 1)
                v += __shfl_down_sync(0xffffffffu, v, off);
            if (tid == 0) atomicAdd(&g_sum, (double)v * 0.125);
        }
        // drain the still-outstanding prefetch group before exiting
        asm volatile("cp.async.wait_group 0;\n");
    }

    // every block (including empty tiles) participates in the finish counter
    if (tid == 0) {
        __threadfence();
        int total = gridDim.x * gridDim.y;
        int old = atomicAdd(&g_done, 1);
        if (old == total - 1) {
            double v = atomicAdd(&g_sum, 0.0);   // coherent read
            out[0] = (float)v;
            g_sum  = 0.0;                        // reset for next call
            g_done = 0;
            for (int i = 0; i < S_; i++) g_cnt[i] = 0;
            __threadfence();
        }
    }
}

extern "C" void kernel_launch(void* const* d_in, const int* in_sizes, int n_in,
                              void* d_out, int out_size) {
    const float* aev     = (const float*)d_in[0];
    const int*   species = (const int*)  d_in[1];
    const float* W1 = (const float*)d_in[2];
    const float* B1 = (const float*)d_in[3];
    const float* W2 = (const float*)d_in[4];
    const float* B2 = (const float*)d_in[5];
    const float* W3 = (const float*)d_in[6];
    const float* B3 = (const float*)d_in[7];
    const float* W4 = (const float*)d_in[8];
    const float* B4 = (const float*)d_in[9];
    float* out = (float*)d_out;

    int n = in_sizes[1];
    if (n > NMAX) n = NMAX;

    const size_t smem = (size_t)(D0 + D1 + D2) * PAD * sizeof(float)
                      + (size_t)2 * KC * D1 * sizeof(float)
                      + (size_t)(D1 + D2 + D3) * sizeof(float)
                      + (size_t)D3 * sizeof(float)
                      + (size_t)TM * sizeof(float)
                      + (size_t)TM * sizeof(int);     // ~226 KB

    cudaFuncSetAttribute(k_compute, cudaFuncAttributeMaxDynamicSharedMemorySize, (int)smem);

    k_bin<<<(n + 511) / 512, 512>>>(species, n);
    const int tiles = (n + TM - 1) / TM;
    k_compute<<<dim3(tiles, S_), NT, smem>>>(aev, W1, B1, W2, B2, W3, B3, W4, B4, out);
}

// round 8
// speedup vs baseline: 1.5736x; 1.5736x over previous
#include <cuda_runtime.h>
#include <math.h>

// ---------------------------------------------------------------------------
// ANI ensemble MLP energy on GB300 (fp32 SIMT with packed fma.rn.f32x2).
// 2-launch cycle: k_bin -> k_compute. Last compute block writes the scalar
// and resets device globals (statics zero-init for call #1).
// Output = sum_a mean_e net_{species[a]}^{(e)}(aev[a]).
// ---------------------------------------------------------------------------

#define NMAX 100000
constexpr int S_ = 4;
constexpr int E_ = 8;
constexpr int D0 = 384, D1 = 160, D2 = 128, D3 = 96;
constexpr int TM = 64;        // atoms per block
constexpr int PAD = 68;       // smem activation row stride (floats)
constexpr int KC = 32;        // K-chunk for weight staging
constexpr int NT = 512;       // 16 warps: warp = output group, lane = 2 atoms

using u64 = unsigned long long;

__device__ int    g_cnt[S_];      // zero-initialized
__device__ int    g_idx[S_ * NMAX];
__device__ double g_sum;          // zero-initialized
__device__ int    g_done;         // zero-initialized

__global__ void k_bin(const int* __restrict__ species, int n) {
    int i = blockIdx.x * blockDim.x + threadIdx.x;
    int lane = threadIdx.x & 31;
    unsigned active = __ballot_sync(0xffffffffu, i < n);
    if (i < n) {
        int s = species[i] & (S_ - 1);
        unsigned peers = __match_any_sync(active, s);
        int leader = __ffs(peers) - 1;
        int rank = __popc(peers & ((1u << lane) - 1));
        int base = 0;
        if (lane == leader) base = atomicAdd(&g_cnt[s], __popc(peers));
        base = __shfl_sync(peers, base, leader);
        g_idx[s * NMAX + base + rank] = i;
    }
}

__device__ __forceinline__ float celu_f(float x) {
    // jax.nn.celu(x, 0.1) = x>0 ? x : 0.1*expm1(x/0.1)
    return x > 0.0f ? x : 0.1f * expm1f(x * 10.0f);
}

__device__ __forceinline__ u64 splat2(float x) {
    u64 r; asm("mov.b64 %0, {%1, %1};" : "=l"(r) : "f"(x)); return r;
}
__device__ __forceinline__ u64 fma2(u64 a, u64 b, u64 c) {
    u64 d; asm("fma.rn.f32x2 %0, %1, %2, %3;" : "=l"(d) : "l"(a), "l"(b), "l"(c));
    return d;
}
__device__ __forceinline__ float2 unpk(u64 a) {
    float2 f; asm("mov.b64 {%0, %1}, %2;" : "=f"(f.x), "=f"(f.y) : "l"(a));
    return f;
}

__device__ __forceinline__ void cp16(float* smem_dst, const float4* gsrc) {
    unsigned a = (unsigned)__cvta_generic_to_shared(smem_dst);
    asm volatile("cp.async.cg.shared.global [%0], [%1], 16;\n" :: "r"(a), "l"(gsrc));
}
__device__ __forceinline__ void cp_commit() {
    asm volatile("cp.async.commit_group;\n");
}

// One dense layer: sOut[n][atom] = celu(sIn[k][atom] @ gW[K][N] + sB[n]).
// Activations transposed [feature][atom], stride PAD.
// warp wid (0..15) owns outputs TN*wid..TN*wid+TN-1; lane owns atoms 2l,2l+1.
// Inner loop: packed f32x2 FMA; acc[atom][j] packs outputs (2j, 2j+1).
template<int K, int N, int TN>
__device__ __forceinline__ void gemm_layer(
    const float* __restrict__ sIn, const float* __restrict__ gW,
    const float* __restrict__ sB, float* __restrict__ sOut,
    float* __restrict__ sW0, float* __restrict__ sW1,
    int tid, int lane, int wid) {

    static_assert((TN & 1) == 0, "TN even: acc packs output pairs");
    constexpr int C   = K / KC;       // chunks
    constexpr int NV4 = KC * N / 4;   // float4 per chunk
    constexpr int TNH = TN / 2;

    u64 acc[2][TNH];
#pragma unroll
    for (int i = 0; i < 2; i++)
#pragma unroll
        for (int j = 0; j < TNH; j++) acc[i][j] = 0ull;

    const float4* gW4 = reinterpret_cast<const float4*>(gW);
    float* bufs[2] = { sW0, sW1 };

    // prefetch chunk 0
    for (int l = tid; l < NV4; l += NT) cp16(sW0 + 4 * l, gW4 + l);
    cp_commit();

    int p = 0;
    for (int c = 0; c < C; c++) {
        if (c + 1 < C) {
            float* dst = bufs[p ^ 1];
            const float4* src = gW4 + (size_t)(c + 1) * NV4;
            for (int l = tid; l < NV4; l += NT) cp16(dst + 4 * l, src + l);
            cp_commit();
            asm volatile("cp.async.wait_group 1;\n");
        } else {
            asm volatile("cp.async.wait_group 0;\n");
        }
        __syncthreads();

        const float* sW = bufs[p];
        const float* inBase = sIn + c * KC * PAD + 2 * lane;
#pragma unroll 4
        for (int kk = 0; kk < KC; kk++) {
            float2 av = *reinterpret_cast<const float2*>(inBase + kk * PAD);
            u64 a0 = splat2(av.x);
            u64 a1 = splat2(av.y);
            // weight pairs (2j,2j+1) as b64 broadcast loads (8B-aligned: TN even)
            const u64* wr = reinterpret_cast<const u64*>(sW + kk * N + TN * wid);
            u64 w[TNH];
#pragma unroll
            for (int j = 0; j < TNH; j++) w[j] = wr[j];
#pragma unroll
            for (int j = 0; j < TNH; j++) {
                acc[0][j] = fma2(a0, w[j], acc[0][j]);
                acc[1][j] = fma2(a1, w[j], acc[1][j]);
            }
        }
        __syncthreads();
        p ^= 1;
    }

    // epilogue: bias + CELU, write transposed (2 atoms -> STS.64)
#pragma unroll
    for (int j = 0; j < TNH; j++) {
        float2 b2 = *reinterpret_cast<const float2*>(sB + TN * wid + 2 * j);
        float2 v0 = unpk(acc[0][j]);   // atom0: outputs 2j, 2j+1
        float2 v1 = unpk(acc[1][j]);   // atom1
        float2 o0, o1;
        o0.x = celu_f(v0.x + b2.x);  o0.y = celu_f(v1.x + b2.x);   // row 2j
        o1.x = celu_f(v0.y + b2.y);  o1.y = celu_f(v1.y + b2.y);   // row 2j+1
        *reinterpret_cast<float2*>(sOut + (TN * wid + 2 * j)     * PAD + 2 * lane) = o0;
        *reinterpret_cast<float2*>(sOut + (TN * wid + 2 * j + 1) * PAD + 2 * lane) = o1;
    }
    __syncthreads();
}

__global__ void __launch_bounds__(NT, 1)
k_compute(const float* __restrict__ aev,
          const float* __restrict__ W1, const float* __restrict__ B1,
          const float* __restrict__ W2, const float* __restrict__ B2,
          const float* __restrict__ W3, const float* __restrict__ B3,
          const float* __restrict__ W4, const float* __restrict__ B4,
          float* __restrict__ out) {
    extern __shared__ float sm[];
    float* sA     = sm;                   // D0*PAD (AEV, persists all ensembles)
    float* sHa    = sA  + D0 * PAD;       // D1*PAD (H1, later H3)
    float* sHb    = sHa + D1 * PAD;       // D2*PAD (H2)
    float* sW0    = sHb + D2 * PAD;       // KC*D1
    float* sW1    = sW0 + KC * D1;        // KC*D1
    float* sBias  = sW1 + KC * D1;        // D1+D2+D3 floats
    float* sW4b   = sBias + (D1 + D2 + D3);
    float* sAtomE = sW4b + D3;
    int*   sIdx   = reinterpret_cast<int*>(sAtomE + TM);

    const int s    = blockIdx.y;
    const int tid  = threadIdx.x;
    const int lane = tid & 31;
    const int wid  = tid >> 5;
    const int cnt  = g_cnt[s];
    const int base = blockIdx.x * TM;

    if (base < cnt) {
        const int nvalid = min(TM, cnt - base);

        if (tid < TM) {
            int j = min(tid, nvalid - 1);   // padding atoms duplicate a valid one
            sIdx[tid]   = g_idx[s * NMAX + base + j];
            sAtomE[tid] = 0.0f;
        }
        __syncthreads();

        // Gather AEV tile, store transposed [k][atom]
        constexpr int KV = D0 / 4;
        const float4* aev4 = reinterpret_cast<const float4*>(aev);
        for (int l = tid; l < TM * KV; l += NT) {
            int a = l / KV, kq = l % KV;
            float4 v = aev4[(long)sIdx[a] * KV + kq];
            int kb = 4 * kq;
            sA[(kb + 0) * PAD + a] = v.x;
            sA[(kb + 1) * PAD + a] = v.y;
            sA[(kb + 2) * PAD + a] = v.z;
            sA[(kb + 3) * PAD + a] = v.w;
        }
        __syncthreads();

        for (int e = 0; e < E_; e++) {
            const int se = s * E_ + e;

            // stage biases + final-layer weights
            if (tid < D1)                sBias[tid] = B1[se * D1 + tid];
            else if (tid < D1 + D2)      sBias[tid] = B2[se * D2 + tid - D1];
            else if (tid < D1 + D2 + D3) sBias[tid] = B3[se * D3 + tid - D1 - D2];
            if (tid >= NT - D3) sW4b[tid - (NT - D3)] = W4[se * D3 + tid - (NT - D3)];
            __syncthreads();

            gemm_layer<D0, D1, 10>(sA,  W1 + (long)se * D0 * D1, sBias,           sHa,
                                   sW0, sW1, tid, lane, wid);
            gemm_layer<D1, D2,  8>(sHa, W2 + (long)se * D1 * D2, sBias + D1,      sHb,
                                   sW0, sW1, tid, lane, wid);
            gemm_layer<D2, D3,  6>(sHb, W3 + (long)se * D2 * D3, sBias + D1 + D2, sHa,
                                   sW0, sW1, tid, lane, wid);

            // final layer: per-atom dot(h3, w4) + b4; 8 threads per atom
            const float gb4 = B4[se];
            int atom = tid >> 3, q = tid & 7;
            float v = 0.0f;
#pragma unroll
            for (int m = 0; m < 12; m++) {
                int k = q * 12 + m;
                v += sHa[k * PAD + atom] * sW4b[k];
            }
            v += __shfl_xor_sync(0xffffffffu, v, 1);
            v += __shfl_xor_sync(0xffffffffu, v, 2);
            v += __shfl_xor_sync(0xffffffffu, v, 4);
            if (q == 0) sAtomE[atom] += v + gb4;
            __syncthreads();
        }

        // block reduction over valid atoms; mean over E via *0.125
        if (tid < 32) {
            float v = 0.0f;
            if (tid < nvalid)      v += sAtomE[tid];
            if (tid + 32 < nvalid) v += sAtomE[tid + 32];
#pragma unroll
            for (int off = 16; off > 0; off >>= 1)
                v += __shfl_down_sync(0xffffffffu, v, off);
            if (tid == 0) atomicAdd(&g_sum, (double)v * 0.125);
        }
    }

    // every block (including empty tiles) participates in the finish counter
    if (tid == 0) {
        __threadfence();
        int total = gridDim.x * gridDim.y;
        int old = atomicAdd(&g_done, 1);
        if (old == total - 1) {
            double v = atomicAdd(&g_sum, 0.0);   // coherent read
            out[0] = (float)v;
            g_sum  = 0.0;                        // reset for next call
            g_done = 0;
            for (int i = 0; i < S_; i++) g_cnt[i] = 0;
            __threadfence();
        }
    }
}

extern "C" void kernel_launch(void* const* d_in, const int* in_sizes, int n_in,
                              void* d_out, int out_size) {
    const float* aev     = (const float*)d_in[0];
    const int*   species = (const int*)  d_in[1];
    const float* W1 = (const float*)d_in[2];
    const float* B1 = (const float*)d_in[3];
    const float* W2 = (const float*)d_in[4];
    const float* B2 = (const float*)d_in[5];
    const float* W3 = (const float*)d_in[6];
    const float* B3 = (const float*)d_in[7];
    const float* W4 = (const float*)d_in[8];
    const float* B4 = (const float*)d_in[9];
    float* out = (float*)d_out;

    int n = in_sizes[1];
    if (n > NMAX) n = NMAX;

    const size_t smem = (size_t)(D0 + D1 + D2) * PAD * sizeof(float)
                      + (size_t)2 * KC * D1 * sizeof(float)
                      + (size_t)(D1 + D2 + D3) * sizeof(float)
                      + (size_t)D3 * sizeof(float)
                      + (size_t)TM * sizeof(float)
                      + (size_t)TM * sizeof(int);     // ~226 KB

    cudaFuncSetAttribute(k_compute, cudaFuncAttributeMaxDynamicSharedMemorySize, (int)smem);

    k_bin<<<(n + 511) / 512, 512>>>(species, n);
    const int tiles = (n + TM - 1) / TM;
    k_compute<<<dim3(tiles, S_), NT, smem>>>(aev, W1, B1, W2, B2, W3, B3, W4, B4, out);
}